// round 8
// baseline (speedup 1.0000x reference)
#include <cuda_runtime.h>
#include <cstdint>

#define BATCH    1024
#define IN_BITS  4096
#define NUM_LUTS 16384
#define KBITS    6
#define NGROUPS  (BATCH / 32)          // 32 groups of 32 batches
#define LTILE    256                   // luts per tile (transposed table stride)
#define NTHR     512                   // 256 LUTs x 2 batch-halves
#define NXTILES  (NUM_LUTS / LTILE)    // 64
#define NTILES   (NXTILES * NGROUPS)   // 2048 (tile = x*32 + g, g-major)

#define PACK_BLOCKS (NGROUPS * (IN_BITS / 256) * 2)   // 1024 (16-row halves)
#define SIGT_BLOCKS (NUM_LUTS * 64 / 16 / 256)        // 256
#define CONN_BLOCKS ((NUM_LUTS * KBITS + 255) / 256)  // 384

__device__ uint32_t g_bits[NGROUPS][IN_BITS];        // 512 KB
__device__ uint16_t g_conn[NUM_LUTS * KBITS];        // 196 KB
__device__ float    g_sigT[64 * NUM_LUTS];           // 4 MB, TRANSPOSED [idx][lut]

// ---------------------------------------------------------------------------
// Fused prep: [pack | sigmoid+transpose | conn] dispatched on blockIdx.x.
// pack v2: thread owns (column p, 16-row half) -> 16 independent coalesced
// LDGs (MLP 16), stores a uint16 half of the packed word.
// ---------------------------------------------------------------------------
__global__ void __launch_bounds__(256) prep_kernel(const float* __restrict__ x,
                                                   const float* __restrict__ table,
                                                   const int* __restrict__ conn32) {
    const int b = blockIdx.x;
    if (b < PACK_BLOCKS) {
        const int g    = b >> 5;
        const int rest = b & 31;
        const int half = rest >> 4;
        const int p    = (rest & 15) * 256 + threadIdx.x;
        const float* xp = x + (size_t)(g * 32 + half * 16) * IN_BITS + p;
        uint32_t a = 0;
#pragma unroll
        for (int j = 0; j < 16; ++j)
            a |= (__ldg(xp + (size_t)j * IN_BITS) > 0.5f ? 1u : 0u) << j;
        ((uint16_t*)g_bits)[2 * ((size_t)g * IN_BITS + p) + half] = (uint16_t)a;
    } else if (b < PACK_BLOCKS + SIGT_BLOCKS) {
        // sigmoid + transpose: thread owns a 4-lut x 4-idx patch.
        const int u    = (b - PACK_BLOCKS) * 256 + threadIdx.x;
        const int lut0 = (u & 4095) * 4;
        const int idx0 = (u >> 12) * 4;
        float4 r[4];
#pragma unroll
        for (int rr = 0; rr < 4; ++rr) {
            float4 v = *(const float4*)(table + (size_t)(lut0 + rr) * 64 + idx0);
            r[rr].x = __fdividef(1.0f, 1.0f + __expf(-v.x));
            r[rr].y = __fdividef(1.0f, 1.0f + __expf(-v.y));
            r[rr].z = __fdividef(1.0f, 1.0f + __expf(-v.z));
            r[rr].w = __fdividef(1.0f, 1.0f + __expf(-v.w));
        }
#pragma unroll
        for (int k = 0; k < 4; ++k) {
            float4 o;
            o.x = (&r[0].x)[k]; o.y = (&r[1].x)[k]; o.z = (&r[2].x)[k]; o.w = (&r[3].x)[k];
            *(float4*)(g_sigT + (size_t)(idx0 + k) * NUM_LUTS + lut0) = o;
        }
    } else {
        // conn dtype sniff: JAX w/o x64 emits int32 despite int64 annotation;
        // true int64 LE would have all odd words == 0 (values < 4096).
        uint32_t acc = 0;
#pragma unroll
        for (int s = 1; s < 64; s += 2) acc |= (uint32_t)conn32[s];
        const bool is_i64 = (acc == 0u);
        const int i = (b - PACK_BLOCKS - SIGT_BLOCKS) * 256 + threadIdx.x;
        if (i < NUM_LUTS * KBITS) {
            int v = is_i64 ? conn32[2 * i] : conn32[i];
            g_conn[i] = (uint16_t)v;
        }
    }
}

// ---------------------------------------------------------------------------
// cp.async helpers
// ---------------------------------------------------------------------------
__device__ __forceinline__ void cp_async16(void* smem_dst, const void* gsrc) {
    uint32_t s = (uint32_t)__cvta_generic_to_shared(smem_dst);
    asm volatile("cp.async.cg.shared.global [%0], [%1], 16;\n" :: "r"(s), "l"(gsrc));
}
__device__ __forceinline__ void cp_async_commit() {
    asm volatile("cp.async.commit_group;\n" ::: "memory");
}
__device__ __forceinline__ void cp_async_wait0() {
    asm volatile("cp.async.wait_group 0;\n" ::: "memory");
}

// ---------------------------------------------------------------------------
// Persistent main kernel. Exactly 2 CTAs/SM (grid = 2*SMs), each CTA walks a
// contiguous range of the 2048 (x,g) tiles (g-major: table tile + conn regs
// reload only on x change, <= ~2 per CTA). Bits double-buffered with cp.async
// across consecutive tiles. smem: 2x16 KB bits + 64 KB transposed table.
// ---------------------------------------------------------------------------
__global__ void __launch_bounds__(NTHR, 2) lut_kernel(float* __restrict__ out) {
    extern __shared__ uint32_t smem[];
    uint32_t* sb[2] = { smem, smem + IN_BITS };
    float*    stab  = (float*)(smem + 2 * IN_BITS);   // [64][LTILE]

    const int t = threadIdx.x;
    const int l = t & (LTILE - 1);
    const int h = t >> 8;
    const int jbase = h * 4;

    const int nb    = gridDim.x;
    const int start = (int)(((long long)NTILES * blockIdx.x) / nb);
    const int end   = (int)(((long long)NTILES * (blockIdx.x + 1)) / nb);

    // Prefetch first tile's bit column.
    {
        const int g = start & (NGROUPS - 1);
        const uint4* src = (const uint4*)g_bits[g];
#pragma unroll
        for (int i = t; i < IN_BITS / 4; i += NTHR)
            cp_async16((uint4*)sb[start & 1] + i, src + i);
        cp_async_commit();
    }

    int curx = -1;
    int c0 = 0, c1 = 0, c2 = 0, c3 = 0, c4 = 0, c5 = 0;
    const float* scol = stab + l;

#pragma unroll 1
    for (int tile = start; tile < end; ++tile) {
        const int x = tile >> 5;            // NGROUPS = 32
        const int g = tile & (NGROUPS - 1);

        if (x != curx) {
            if (curx >= 0) __syncthreads();  // prior tile's stab readers done
            const int lutbase = x * LTILE;
#pragma unroll
            for (int i = t; i < 64 * (LTILE / 4); i += NTHR) {
                const int idx = i >> 6, c = (i & 63) * 4;
                *(float4*)(stab + idx * LTILE + c) =
                    *(const float4*)(g_sigT + (size_t)idx * NUM_LUTS + lutbase + c);
            }
            const uint16_t* cp = &g_conn[(size_t)(lutbase + l) * KBITS];
            c0 = cp[0]; c1 = cp[1]; c2 = cp[2]; c3 = cp[3]; c4 = cp[4]; c5 = cp[5];
            curx = x;
        }

        cp_async_wait0();
        __syncthreads();                     // bits + (maybe) stab visible

        // Prefetch next tile's bits into the other buffer.
        if (tile + 1 < end) {
            const int gn = (tile + 1) & (NGROUPS - 1);
            const uint4* src = (const uint4*)g_bits[gn];
#pragma unroll
            for (int i = t; i < IN_BITS / 4; i += NTHR)
                cp_async16((uint4*)sb[(tile + 1) & 1] + i, src + i);
            cp_async_commit();
        }

        const uint32_t* cur = sb[tile & 1];
        const uint32_t w0 = cur[c0], w1 = cur[c1], w2 = cur[c2];
        const uint32_t w3 = cur[c3], w4 = cur[c4], w5 = cur[c5];

        float* op = out + (size_t)(g * 32 + jbase) * NUM_LUTS + x * LTILE + l;
#pragma unroll
        for (int jj = 0; jj < 4; ++jj) {
            const int j = jbase + jj;
            // four 6-bit indices at once (bits j, j+8, j+16, j+24 of each word)
            uint32_t acc =   ((w0 >> j) & 0x01010101u);
            acc = acc * 2u + ((w1 >> j) & 0x01010101u);
            acc = acc * 2u + ((w2 >> j) & 0x01010101u);
            acc = acc * 2u + ((w3 >> j) & 0x01010101u);
            acc = acc * 2u + ((w4 >> j) & 0x01010101u);
            acc = acc * 2u + ((w5 >> j) & 0x01010101u);
            const unsigned i0 = acc & 0xFFu;
            const unsigned i1 = __byte_perm(acc, 0, 0x4441);
            const unsigned i2 = __byte_perm(acc, 0, 0x4442);
            const unsigned i3 = acc >> 24;
            float v0 = scol[i0 * LTILE];     // conflict-free LDS (bank = lane)
            float v1 = scol[i1 * LTILE];
            float v2 = scol[i2 * LTILE];
            float v3 = scol[i3 * LTILE];
            __stcs(op + (size_t)jj * NUM_LUTS, v0);
            __stcs(op + (size_t)(jj + 8)  * NUM_LUTS, v1);
            __stcs(op + (size_t)(jj + 16) * NUM_LUTS, v2);
            __stcs(op + (size_t)(jj + 24) * NUM_LUTS, v3);
        }

        __syncthreads();                     // cur-buffer reads done before reuse
    }
}

// ---------------------------------------------------------------------------
extern "C" void kernel_launch(void* const* d_in, const int* in_sizes, int n_in,
                              void* d_out, int out_size) {
    const float* x    = (const float*)d_in[0];   // (1024, 4096) f32
    const float* tab  = (const float*)d_in[1];   // (16384, 64) f32
    const int*   conn = (const int*)d_in[2];     // (16384, 6) i32 (sniffed)
    float*       out  = (float*)d_out;           // (1024, 16384) f32

    int sms = 0;
    cudaDeviceGetAttribute(&sms, cudaDevAttrMultiProcessorCount, 0);
    if (sms <= 0) sms = 148;
    const int nb = 2 * sms;                      // exactly 2 CTAs/SM, 1 wave

    static const int SMEM = (2 * IN_BITS + 64 * LTILE) * 4;  // 98304 B
    cudaFuncSetAttribute(lut_kernel, cudaFuncAttributeMaxDynamicSharedMemorySize, SMEM);

    prep_kernel<<<PACK_BLOCKS + SIGT_BLOCKS + CONN_BLOCKS, 256>>>(x, tab, conn);

    lut_kernel<<<nb, NTHR, SMEM>>>(out);
}

// round 9
// speedup vs baseline: 1.0051x; 1.0051x over previous
#include <cuda_runtime.h>
#include <cstdint>

#define BATCH    1024
#define IN_BITS  4096
#define NUM_LUTS 16384
#define KBITS    6
#define NGROUPS  (BATCH / 32)          // 32 groups of 32 batches
#define LTILE    256                   // luts per tile
#define NTHR     512                   // 256 LUTs x 2 batch-halves
#define NXTILES  (NUM_LUTS / LTILE)    // 64
#define NTILES   (NXTILES * NGROUPS)   // 2048, g-major: tile = x*32 + g

#define PACK_BLOCKS (NGROUPS * (IN_BITS / 256) * 2)   // 1024
#define SIGT_BLOCKS (NUM_LUTS * 64 / 16 / 256)        // 256
#define CONN_BLOCKS ((NUM_LUTS * KBITS + 255) / 256)  // 384

__device__ uint32_t g_bits[NGROUPS][IN_BITS];        // 512 KB
__device__ uint16_t g_conn[NUM_LUTS * KBITS];        // 196 KB
__device__ float    g_sigT[64 * NUM_LUTS];           // 4 MB, TRANSPOSED [idx][lut]

// ---------------------------------------------------------------------------
// Fused prep: [pack | sigmoid+transpose | conn] dispatched on blockIdx.x.
// ---------------------------------------------------------------------------
__global__ void __launch_bounds__(256) prep_kernel(const float* __restrict__ x,
                                                   const float* __restrict__ table,
                                                   const int* __restrict__ conn32) {
    const int b = blockIdx.x;
    if (b < PACK_BLOCKS) {
        const int g    = b >> 5;
        const int rest = b & 31;
        const int half = rest >> 4;
        const int p    = (rest & 15) * 256 + threadIdx.x;
        const float* xp = x + (size_t)(g * 32 + half * 16) * IN_BITS + p;
        uint32_t a = 0;
#pragma unroll
        for (int j = 0; j < 16; ++j)
            a |= (__ldg(xp + (size_t)j * IN_BITS) > 0.5f ? 1u : 0u) << j;
        ((uint16_t*)g_bits)[2 * ((size_t)g * IN_BITS + p) + half] = (uint16_t)a;
    } else if (b < PACK_BLOCKS + SIGT_BLOCKS) {
        const int u    = (b - PACK_BLOCKS) * 256 + threadIdx.x;
        const int lut0 = (u & 4095) * 4;
        const int idx0 = (u >> 12) * 4;
        float4 r[4];
#pragma unroll
        for (int rr = 0; rr < 4; ++rr) {
            float4 v = *(const float4*)(table + (size_t)(lut0 + rr) * 64 + idx0);
            r[rr].x = __fdividef(1.0f, 1.0f + __expf(-v.x));
            r[rr].y = __fdividef(1.0f, 1.0f + __expf(-v.y));
            r[rr].z = __fdividef(1.0f, 1.0f + __expf(-v.z));
            r[rr].w = __fdividef(1.0f, 1.0f + __expf(-v.w));
        }
#pragma unroll
        for (int k = 0; k < 4; ++k) {
            float4 o;
            o.x = (&r[0].x)[k]; o.y = (&r[1].x)[k]; o.z = (&r[2].x)[k]; o.w = (&r[3].x)[k];
            *(float4*)(g_sigT + (size_t)(idx0 + k) * NUM_LUTS + lut0) = o;
        }
    } else {
        // conn dtype sniff: JAX w/o x64 emits int32 despite int64 annotation;
        // true int64 LE would have all odd words == 0 (values < 4096).
        uint32_t acc = 0;
#pragma unroll
        for (int s = 1; s < 64; s += 2) acc |= (uint32_t)conn32[s];
        const bool is_i64 = (acc == 0u);
        const int i = (b - PACK_BLOCKS - SIGT_BLOCKS) * 256 + threadIdx.x;
        if (i < NUM_LUTS * KBITS) {
            int v = is_i64 ? conn32[2 * i] : conn32[i];
            g_conn[i] = (uint16_t)v;
        }
    }
}

// ---------------------------------------------------------------------------
// cp.async helpers
// ---------------------------------------------------------------------------
__device__ __forceinline__ void cp_async16(void* smem_dst, const void* gsrc) {
    uint32_t s = (uint32_t)__cvta_generic_to_shared(smem_dst);
    asm volatile("cp.async.cg.shared.global [%0], [%1], 16;\n" :: "r"(s), "l"(gsrc));
}
__device__ __forceinline__ void cp_async_commit() {
    asm volatile("cp.async.commit_group;\n" ::: "memory");
}
__device__ __forceinline__ void cp_async_wait0() {
    asm volatile("cp.async.wait_group 0;\n" ::: "memory");
}

// ---------------------------------------------------------------------------
// Persistent main kernel, grid = 2*SMs. Tiles (g-major) split contiguously.
// Outer loop over x (<=2 per CTA): straight-line table/conn reload.
// Inner loop over g: ONE __syncthreads per tile:
//   [wait0][sync][issue prefetch next][compute]
// The single sync simultaneously (a) makes this tile's cp.async bits visible
// block-wide, (b) publishes any just-written table tile, (c) guards reuse of
// the other buffer (its next write is issued only after the FOLLOWING sync).
// ---------------------------------------------------------------------------
__global__ void __launch_bounds__(NTHR, 2) lut_kernel(float* __restrict__ out) {
    extern __shared__ uint32_t smem[];
    float* stab = (float*)(smem + 2 * IN_BITS);   // [64][LTILE]

    const int t = threadIdx.x;
    const int l = t & (LTILE - 1);
    const int h = t >> 8;
    const int jbase = h * 4;

    const int nb    = gridDim.x;
    const int start = (int)(((long long)NTILES * blockIdx.x) / nb);
    const int end   = (int)(((long long)NTILES * (blockIdx.x + 1)) / nb);
    if (start >= end) return;

    // Prime: prefetch first tile's bit column into buffer A.
    uint32_t* bufA = smem;                        // holds bits for 'tile'
    uint32_t* bufB = smem + IN_BITS;              // prefetch target
    {
        const uint4* src = (const uint4*)g_bits[start & (NGROUPS - 1)];
#pragma unroll
        for (int i = t; i < IN_BITS / 4; i += NTHR)
            cp_async16((uint4*)bufA + i, src + i);
        cp_async_commit();
    }

    const float* scol = stab + l;
    int tile = start;

#pragma unroll 1
    for (int x = start >> 5; x <= (end - 1) >> 5; ++x) {
        // Load this x's transposed table tile (overlaps outstanding cp.async).
        const int lutbase = x * LTILE;
#pragma unroll
        for (int i = t; i < 64 * (LTILE / 4); i += NTHR) {
            const int idx = i >> 6, c = (i & 63) * 4;
            *(float4*)(stab + idx * LTILE + c) =
                *(const float4*)(g_sigT + (size_t)idx * NUM_LUTS + lutbase + c);
        }
        const uint16_t* cp = &g_conn[(size_t)(lutbase + l) * KBITS];
        const int c0 = cp[0], c1 = cp[1], c2 = cp[2];
        const int c3 = cp[3], c4 = cp[4], c5 = cp[5];

        const int gend = min(end, (x + 1) * NGROUPS);   // tile limit for this x

#pragma unroll 1
        for (; tile < gend; ++tile) {
            cp_async_wait0();
            __syncthreads();          // bits + stab visible; prior reads done

            if (tile + 1 < end) {
                const uint4* src = (const uint4*)g_bits[(tile + 1) & (NGROUPS - 1)];
#pragma unroll
                for (int i = t; i < IN_BITS / 4; i += NTHR)
                    cp_async16((uint4*)bufB + i, src + i);
                cp_async_commit();
            }

            const uint32_t w0 = bufA[c0], w1 = bufA[c1], w2 = bufA[c2];
            const uint32_t w3 = bufA[c3], w4 = bufA[c4], w5 = bufA[c5];

            const int g = tile & (NGROUPS - 1);
            float* op = out + (size_t)(g * 32 + jbase) * NUM_LUTS + lutbase + l;
#pragma unroll
            for (int jj = 0; jj < 4; ++jj) {
                const int j = jbase + jj;
                // four 6-bit indices at once (bits j, j+8, j+16, j+24)
                uint32_t acc =   ((w0 >> j) & 0x01010101u);
                acc = acc * 2u + ((w1 >> j) & 0x01010101u);
                acc = acc * 2u + ((w2 >> j) & 0x01010101u);
                acc = acc * 2u + ((w3 >> j) & 0x01010101u);
                acc = acc * 2u + ((w4 >> j) & 0x01010101u);
                acc = acc * 2u + ((w5 >> j) & 0x01010101u);
                const unsigned i0 = acc & 0xFFu;
                const unsigned i1 = __byte_perm(acc, 0, 0x4441);
                const unsigned i2 = __byte_perm(acc, 0, 0x4442);
                const unsigned i3 = acc >> 24;
                float v0 = scol[i0 * LTILE];     // conflict-free (bank = lane)
                float v1 = scol[i1 * LTILE];
                float v2 = scol[i2 * LTILE];
                float v3 = scol[i3 * LTILE];
                __stcs(op + (size_t)jj * NUM_LUTS, v0);
                __stcs(op + (size_t)(jj + 8)  * NUM_LUTS, v1);
                __stcs(op + (size_t)(jj + 16) * NUM_LUTS, v2);
                __stcs(op + (size_t)(jj + 24) * NUM_LUTS, v3);
            }

            // swap buffers: bufB (just prefetched) becomes current
            uint32_t* tmp = bufA; bufA = bufB; bufB = tmp;
        }
    }
}

// ---------------------------------------------------------------------------
extern "C" void kernel_launch(void* const* d_in, const int* in_sizes, int n_in,
                              void* d_out, int out_size) {
    const float* x    = (const float*)d_in[0];   // (1024, 4096) f32
    const float* tab  = (const float*)d_in[1];   // (16384, 64) f32
    const int*   conn = (const int*)d_in[2];     // (16384, 6) i32 (sniffed)
    float*       out  = (float*)d_out;           // (1024, 16384) f32

    int sms = 0;
    cudaDeviceGetAttribute(&sms, cudaDevAttrMultiProcessorCount, 0);
    if (sms <= 0) sms = 148;
    const int nb = 2 * sms;

    static const int SMEM = (2 * IN_BITS + 64 * LTILE) * 4;  // 98304 B
    cudaFuncSetAttribute(lut_kernel, cudaFuncAttributeMaxDynamicSharedMemorySize, SMEM);

    prep_kernel<<<PACK_BLOCKS + SIGT_BLOCKS + CONN_BLOCKS, 256>>>(x, tab, conn);

    lut_kernel<<<nb, NTHR, SMEM>>>(out);
}

// round 10
// speedup vs baseline: 1.0755x; 1.0701x over previous
#include <cuda_runtime.h>
#include <cstdint>

#define BATCH    1024
#define IN_BITS  4096
#define NUM_LUTS 16384
#define KBITS    6
#define NGROUPS  (BATCH / 32)          // 32 groups of 32 batches
#define LTILE    256                   // luts per block (transposed tile stride)
#define NTHR     512                   // 256 LUTs x 2 batch-halves
#define BC       8                     // batch-groups per block

#define PACK_BLOCKS (NGROUPS * (IN_BITS / 256) * 2)   // 1024 (16-row halves)
#define SIGT_BLOCKS (NUM_LUTS / 64)                   // 256 (64-lut patches)
#define CONN_BLOCKS ((NUM_LUTS * KBITS + 255) / 256)  // 384

__device__ uint32_t g_bits[NGROUPS][IN_BITS];        // 512 KB
__device__ uint16_t g_conn[NUM_LUTS * KBITS];        // 196 KB
__device__ float    g_sigT[64 * NUM_LUTS];           // 4 MB, TRANSPOSED [idx][lut]

// ---------------------------------------------------------------------------
// Fused prep: [pack | sigmoid+smem-transpose | conn] dispatched on blockIdx.x.
// ---------------------------------------------------------------------------
__global__ void __launch_bounds__(256) prep_kernel(const float* __restrict__ x,
                                                   const float* __restrict__ table,
                                                   const int* __restrict__ conn32) {
    __shared__ float s[64 * 65];   // [idx][lut] patch, pad 65 (<=2-way conflicts)
    const int b = blockIdx.x;
    if (b < PACK_BLOCKS) {
        // pack v2: thread owns (column p, 16-row half) -> MLP 16 coalesced LDGs
        const int g    = b >> 5;
        const int rest = b & 31;
        const int half = rest >> 4;
        const int p    = (rest & 15) * 256 + threadIdx.x;
        const float* xp = x + (size_t)(g * 32 + half * 16) * IN_BITS + p;
        uint32_t a = 0;
#pragma unroll
        for (int j = 0; j < 16; ++j)
            a |= (__ldg(xp + (size_t)j * IN_BITS) > 0.5f ? 1u : 0u) << j;
        ((uint16_t*)g_bits)[2 * ((size_t)g * IN_BITS + p) + half] = (uint16_t)a;
    } else if (b < PACK_BLOCKS + SIGT_BLOCKS) {
        // 64-lut x 64-idx patch: coalesced read -> sigmoid -> smem transpose
        // -> coalesced float4 write to g_sigT[idx][lut].
        const int lut0 = (b - PACK_BLOCKS) * 64;
        const int t = threadIdx.x;
#pragma unroll
        for (int k = 0; k < 4; ++k) {
            const int i = t + k * 256;          // 0..1023
            const int r = i >> 4;               // lut in patch
            const int q = i & 15;               // float4 within row
            float4 v = *(const float4*)(table + (size_t)(lut0 + r) * 64 + 4 * q);
            v.x = __fdividef(1.0f, 1.0f + __expf(-v.x));
            v.y = __fdividef(1.0f, 1.0f + __expf(-v.y));
            v.z = __fdividef(1.0f, 1.0f + __expf(-v.z));
            v.w = __fdividef(1.0f, 1.0f + __expf(-v.w));
            s[(4 * q + 0) * 65 + r] = v.x;
            s[(4 * q + 1) * 65 + r] = v.y;
            s[(4 * q + 2) * 65 + r] = v.z;
            s[(4 * q + 3) * 65 + r] = v.w;
        }
        __syncthreads();
#pragma unroll
        for (int k = 0; k < 4; ++k) {
            const int i = t + k * 256;
            const int c = i >> 4;               // idx row
            const int j = (i & 15) * 4;         // lut quad
            float4 o;
            o.x = s[c * 65 + j + 0];
            o.y = s[c * 65 + j + 1];
            o.z = s[c * 65 + j + 2];
            o.w = s[c * 65 + j + 3];
            *(float4*)(g_sigT + (size_t)c * NUM_LUTS + lut0 + j) = o;
        }
    } else {
        // conn dtype sniff: JAX w/o x64 emits int32 despite int64 annotation;
        // true int64 LE would have all odd words == 0 (values < 4096).
        uint32_t acc = 0;
#pragma unroll
        for (int sI = 1; sI < 64; sI += 2) acc |= (uint32_t)conn32[sI];
        const bool is_i64 = (acc == 0u);
        const int i = (b - PACK_BLOCKS - SIGT_BLOCKS) * 256 + threadIdx.x;
        if (i < NUM_LUTS * KBITS) {
            int v = is_i64 ? conn32[2 * i] : conn32[i];
            g_conn[i] = (uint16_t)v;
        }
    }
}

// ---------------------------------------------------------------------------
// cp.async helpers
// ---------------------------------------------------------------------------
__device__ __forceinline__ void cp_async16(void* smem_dst, const void* gsrc) {
    uint32_t s = (uint32_t)__cvta_generic_to_shared(smem_dst);
    asm volatile("cp.async.cg.shared.global [%0], [%1], 16;\n" :: "r"(s), "l"(gsrc));
}
__device__ __forceinline__ void cp_async_commit() {
    asm volatile("cp.async.commit_group;\n" ::: "memory");
}
__device__ __forceinline__ void cp_async_wait0() {
    asm volatile("cp.async.wait_group 0;\n" ::: "memory");
}

// ---------------------------------------------------------------------------
// Main LUT kernel — round-7 structure verbatim (measured 17.86us, 5.3e-8).
// block = 512 = 256 LUTs x 2 batch-halves, grid (64,4), 2 CTAs/SM.
// smem: 2x16 KB bit buffers (cp.async double-buffered) + 64 KB TRANSPOSED
// table tile stab[idx][l] (stride 256 -> LDS bank = lane -> conflict-free).
// idx build packs FOUR 6-bit indices per acc word (bits j, j+8, j+16, j+24).
// ---------------------------------------------------------------------------
__global__ void __launch_bounds__(NTHR, 2) lut_kernel(float* __restrict__ out) {
    extern __shared__ uint32_t smem[];
    uint32_t* sb0  = smem;                          // bits buffer 0
    uint32_t* sb1  = smem + IN_BITS;                // bits buffer 1
    float*    stab = (float*)(smem + 2 * IN_BITS);  // [64][LTILE]

    const int t       = threadIdx.x;
    const int l       = t & (LTILE - 1);
    const int h       = t >> 8;                     // batch half
    const int lutbase = blockIdx.x * LTILE;
    const int g0      = blockIdx.y * BC;
    const int lut     = lutbase + l;

    // Prefetch g0's bit column (async).
    {
        const uint4* src = (const uint4*)g_bits[g0];
#pragma unroll
        for (int i = t; i < IN_BITS / 4; i += NTHR)
            cp_async16((uint4*)sb0 + i, src + i);
        cp_async_commit();
    }

    // Transposed table tile: stab[idx][l] <- g_sigT[idx][lutbase+l].
    {
#pragma unroll
        for (int i = t; i < 64 * (LTILE / 4); i += NTHR) {
            const int idx = i >> 6, c = (i & 63) * 4;
            *(float4*)(stab + idx * LTILE + c) =
                *(const float4*)(g_sigT + (size_t)idx * NUM_LUTS + lutbase + c);
        }
    }

    const uint16_t* cp = &g_conn[(size_t)lut * KBITS];
    const int c0 = cp[0], c1 = cp[1], c2 = cp[2], c3 = cp[3], c4 = cp[4], c5 = cp[5];
    const float* scol = stab + l;                   // this LUT's column
    const int jbase = h * 4;

    cp_async_wait0();
    __syncthreads();

#pragma unroll 1
    for (int g = g0; g < g0 + BC; ++g) {
        uint32_t* cur = ((g - g0) & 1) ? sb1 : sb0;
        uint32_t* nxt = ((g - g0) & 1) ? sb0 : sb1;

        if (g + 1 < g0 + BC) {
            const uint4* src = (const uint4*)g_bits[g + 1];
#pragma unroll
            for (int i = t; i < IN_BITS / 4; i += NTHR)
                cp_async16((uint4*)nxt + i, src + i);
            cp_async_commit();
        }

        const uint32_t w0 = cur[c0], w1 = cur[c1], w2 = cur[c2];
        const uint32_t w3 = cur[c3], w4 = cur[c4], w5 = cur[c5];

        float* op = out + (size_t)(g * 32 + jbase) * NUM_LUTS + lut;
#pragma unroll
        for (int jj = 0; jj < 4; ++jj) {
            const int j = jbase + jj;
            // four 6-bit indices at once (bits j, j+8, j+16, j+24 of each word)
            uint32_t acc =   ((w0 >> j) & 0x01010101u);
            acc = acc * 2u + ((w1 >> j) & 0x01010101u);
            acc = acc * 2u + ((w2 >> j) & 0x01010101u);
            acc = acc * 2u + ((w3 >> j) & 0x01010101u);
            acc = acc * 2u + ((w4 >> j) & 0x01010101u);
            acc = acc * 2u + ((w5 >> j) & 0x01010101u);
            const unsigned i0 = acc & 0xFFu;
            const unsigned i1 = __byte_perm(acc, 0, 0x4441);
            const unsigned i2 = __byte_perm(acc, 0, 0x4442);
            const unsigned i3 = acc >> 24;
            float v0 = scol[i0 * LTILE];            // conflict-free LDS
            float v1 = scol[i1 * LTILE];
            float v2 = scol[i2 * LTILE];
            float v3 = scol[i3 * LTILE];
            __stcs(op + (size_t)jj * NUM_LUTS, v0);
            __stcs(op + (size_t)(jj + 8)  * NUM_LUTS, v1);
            __stcs(op + (size_t)(jj + 16) * NUM_LUTS, v2);
            __stcs(op + (size_t)(jj + 24) * NUM_LUTS, v3);
        }

        cp_async_wait0();
        __syncthreads();
    }
}

// ---------------------------------------------------------------------------
extern "C" void kernel_launch(void* const* d_in, const int* in_sizes, int n_in,
                              void* d_out, int out_size) {
    const float* x    = (const float*)d_in[0];   // (1024, 4096) f32
    const float* tab  = (const float*)d_in[1];   // (16384, 64) f32
    const int*   conn = (const int*)d_in[2];     // (16384, 6) i32 (sniffed)
    float*       out  = (float*)d_out;           // (1024, 16384) f32

    static const int SMEM = (2 * IN_BITS + 64 * LTILE) * 4;  // 98304 B
    cudaFuncSetAttribute(lut_kernel, cudaFuncAttributeMaxDynamicSharedMemorySize, SMEM);

    prep_kernel<<<PACK_BLOCKS + SIGT_BLOCKS + CONN_BLOCKS, 256>>>(x, tab, conn);

    dim3 gridC(NUM_LUTS / LTILE, NGROUPS / BC);          // (64, 4)
    lut_kernel<<<gridC, NTHR, SMEM>>>(out);
}